// round 9
// baseline (speedup 1.0000x reference)
#include <cuda_runtime.h>
#include <math.h>

#define PI_D 3.14159265358979323846

// ---------------------------------------------------------------------------
// Problem constants: B=8, CI=CO=64, H=W=256, M1=M2=16, G=4, RANK=4, NEXP=15
// Active modes: ki index 0..127 -> H-mode (ki<64 ? ki : ki+128); kj 0..63.
// ---------------------------------------------------------------------------

// Scratch (device globals: no runtime allocation allowed)
__device__ float2 g_T  [256 * 512 * 64];   // [u][bc][kj]   W-DFT of x
__device__ float2 g_X  [128 * 512 * 64];   // [ki][bc][kj]  full corner spectrum
__device__ float2 g_OUT[128 * 512 * 64];   // [ki][bo][kj]  mixed spectrum
__device__ float2 g_Z  [256 * 512 * 64];   // [u][bo][kj]   inverse H-DFT
__device__ float  g_Bw [256 * 128];        // [v][2kj(+1)]  forward W twiddles
__device__ float2 g_A2 [128 * 256];        // [ki][u]       forward H twiddles
__device__ float2 g_A3 [256 * 128];        // [u][ki]       inverse H twiddles
__device__ float  g_Bi [128 * 256];        // [2kj(+1)][v]  inverse W (Hermitian-folded, /HW)
__device__ float2 g_Wt [2 * 256 * 64 * 64];        // [t][xy][i][o] base weights transposed
__device__ float2 g_LBt[2 * 15 * 256 * 64 * 4];    // [s][e][xy][o][r] lora_b transposed

__device__ __forceinline__ float2 cmad(float2 acc, float2 a, float2 b) {
    acc.x = fmaf(a.x, b.x, fmaf(-a.y, b.y, acc.x));
    acc.y = fmaf(a.x, b.y, fmaf( a.y, b.x, acc.y));
    return acc;
}

// ---------------------------------------------------------------------------
// Twiddle tables (built per launch; deterministic)
// ---------------------------------------------------------------------------
__global__ void prep_tables() {
    int idx = blockIdx.x * 256 + threadIdx.x;   // 0..32767
    const double w = 2.0 * PI_D / 256.0;
    {   // Bw[v][n]: n=2kj -> cos, n=2kj+1 -> -sin  (e^{-i t})
        int v = idx >> 7, n = idx & 127, kj = n >> 1;
        double s, c; sincos(w * ((kj * v) & 255), &s, &c);
        g_Bw[idx] = (n & 1) ? (float)(-s) : (float)c;
    }
    {   // A2[ki][u] = e^{-2pi i m u / 256}
        int ki = idx >> 8, u = idx & 255;
        int m = (ki < 64) ? ki : ki + 128;
        double s, c; sincos(w * ((m * u) & 255), &s, &c);
        g_A2[idx] = make_float2((float)c, (float)(-s));
    }
    {   // A3[u][ki] = e^{+2pi i m u / 256}
        int u = idx >> 7, ki = idx & 127;
        int m = (ki < 64) ? ki : ki + 128;
        double s, c; sincos(w * ((m * u) & 255), &s, &c);
        g_A3[idx] = make_float2((float)c, (float)s);
    }
    {   // Bi[n][v]: y = sum_kj Re*z*C + Im*z*S; C0=inv, Ck=2 inv cos, S0=0, Sk=-2 inv sin
        int n = idx >> 8, v = idx & 255, kj = n >> 1;
        double s, c; sincos(w * ((kj * v) & 255), &s, &c);
        const float inv = 1.0f / 65536.0f;
        float val;
        if ((n & 1) == 0) val = (kj == 0) ? inv : (float)(2.0 * c) * inv;
        else              val = (kj == 0) ? 0.f : (float)(-2.0 * s) * inv;
        g_Bi[idx] = val;
    }
}

// Transpose base weights: w[i][o][xy] -> Wt[t][xy][i*64+o]
__global__ void prep_w(const float* __restrict__ w1re, const float* __restrict__ w1im,
                       const float* __restrict__ w2re, const float* __restrict__ w2im) {
    int idx = blockIdx.x * 256 + threadIdx.x;          // 0 .. 2*256*4096-1
    int t   = idx >> 20;
    int xy  = (idx >> 12) & 255;
    int io  = idx & 4095;
    int i   = io >> 6, o = io & 63;
    int src = i * 16384 + o * 256 + xy;
    const float* re = t ? w2re : w1re;
    const float* im = t ? w2im : w1im;
    g_Wt[idx] = make_float2(re[src], im[src]);
}

// Transpose lora_b: lb[e][o][r][xy] -> LBt[s][e][xy][o*4+r]
__global__ void prep_lb(const float* __restrict__ b1re, const float* __restrict__ b1im,
                        const float* __restrict__ b2re, const float* __restrict__ b2im) {
    int idx = blockIdx.x * 256 + threadIdx.x;          // 0 .. 1966080-1
    int s   = idx / 983040;
    int rem = idx - s * 983040;
    int e   = rem >> 16;
    int rem2 = rem & 65535;
    int xy  = rem2 >> 8;
    int orr = rem2 & 255;
    int o   = orr >> 2, r = orr & 3;
    int src = e * 65536 + o * 1024 + r * 256 + xy;
    const float* re = s ? b2re : b1re;
    const float* im = s ? b2im : b1im;
    g_LBt[idx] = make_float2(re[src], im[src]);
}

// ---------------------------------------------------------------------------
// Real SGEMM, 64x128 block, 32 K-tile, 8x4 microtile, double-buffered smem.
// MODE 0 (K1):  A = x rows [r*256], K=256, N=128, C = g_T with row perm (bc,u)->(u,bc)
// MODE 1 (K4):  A = g_Z with row perm (bo,u)->(u,bo), K=128, N=256, C = y natural
// ---------------------------------------------------------------------------
template<int MODE>
__global__ __launch_bounds__(256) void sgemm_dft(const float* __restrict__ Ain,
                                                 float* __restrict__ Cout) {
    const int K = (MODE == 0) ? 256 : 128;
    const int N = (MODE == 0) ? 128 : 256;
    const int T = K / 32;
    const float* __restrict__ A  = (MODE == 0) ? Ain : (const float*)g_Z;
    const float* __restrict__ Bm = (MODE == 0) ? g_Bw : g_Bi;
    float* __restrict__ C        = (MODE == 0) ? (float*)g_T : Cout;

    __shared__ float As[2][32][64];
    __shared__ float Bs[2][32][128];

    const int mBase = blockIdx.x * 64;
    const int nBase = blockIdx.y * 128;
    const int tid = threadIdx.x;
    const int mg = tid >> 5;        // 0..7
    const int ng = tid & 31;        // 0..31

    float4 pA[2], pB[4];

    // Prefetch tile at k0 into registers (addresses identical to audited version)
    auto loadRegs = [&](int k0) {
#pragma unroll
        for (int j = 0; j < 2; j++) {
            int lid = tid * 2 + j;                 // 0..511
            int row = lid >> 3;
            int k4  = (lid & 7) * 4;
            int gr  = mBase + row;
            const float* arow;
            if (MODE == 0) arow = A + (size_t)gr * 256;
            else           arow = A + ((size_t)(gr & 255) * 512 + (gr >> 8)) * 128;
            pA[j] = *(const float4*)(arow + k0 + k4);
        }
#pragma unroll
        for (int j = 0; j < 4; j++) {
            int lid = tid + 256 * j;               // 0..1023
            int row = lid >> 5;
            int c4  = (lid & 31) * 4;
            pB[j] = *(const float4*)(Bm + (size_t)(k0 + row) * N + nBase + c4);
        }
    };
    auto storeRegs = [&](int buf) {
#pragma unroll
        for (int j = 0; j < 2; j++) {
            int lid = tid * 2 + j;
            int row = lid >> 3;
            int k4  = (lid & 7) * 4;
            As[buf][k4 + 0][row] = pA[j].x; As[buf][k4 + 1][row] = pA[j].y;
            As[buf][k4 + 2][row] = pA[j].z; As[buf][k4 + 3][row] = pA[j].w;
        }
#pragma unroll
        for (int j = 0; j < 4; j++) {
            int lid = tid + 256 * j;
            int row = lid >> 5;
            int c4  = (lid & 31) * 4;
            *(float4*)&Bs[buf][row][c4] = pB[j];
        }
    };

    float acc[8][4];
#pragma unroll
    for (int i = 0; i < 8; i++)
#pragma unroll
        for (int j = 0; j < 4; j++) acc[i][j] = 0.f;

    loadRegs(0);
    storeRegs(0);
    __syncthreads();

    for (int t = 0; t < T; t++) {
        if (t + 1 < T) loadRegs((t + 1) * 32);
        const int cur = t & 1;
#pragma unroll
        for (int kk = 0; kk < 32; kk++) {
            float rA[8], rB[4];
#pragma unroll
            for (int j = 0; j < 8; j++) rA[j] = As[cur][kk][mg * 8 + j];
#pragma unroll
            for (int j = 0; j < 4; j++) rB[j] = Bs[cur][kk][ng * 4 + j];
#pragma unroll
            for (int i = 0; i < 8; i++)
#pragma unroll
                for (int j = 0; j < 4; j++) acc[i][j] = fmaf(rA[i], rB[j], acc[i][j]);
        }
        if (t + 1 < T) storeRegs((t + 1) & 1);
        __syncthreads();
    }

#pragma unroll
    for (int i = 0; i < 8; i++) {
        int gr = mBase + mg * 8 + i;
        float* crow;
        if (MODE == 0) {
            int bc = gr >> 8, u = gr & 255;
            crow = C + (size_t)(u * 512 + bc) * 128;
        } else {
            crow = C + (size_t)gr * 256;
        }
        *(float4*)(crow + nBase + ng * 4) =
            make_float4(acc[i][0], acc[i][1], acc[i][2], acc[i][3]);
    }
}

// ---------------------------------------------------------------------------
// Complex GEMM: C[M][32768] = A[M][K] * B[K][32768].  128x32 block, 16 K-tile,
// 8x2 complex microtile, double-buffered smem.
// PHASE 0: K2 (A2 * T -> X).  PHASE 1: K3 (A3 * OUT -> Z).
// ---------------------------------------------------------------------------
template<int PHASE>
__global__ __launch_bounds__(256) void cgemm_dft() {
    const int K = (PHASE == 0) ? 256 : 128;
    const int N = 32768;
    const int T = K / 16;
    const float2* __restrict__ A = (PHASE == 0) ? g_A2 : g_A3;
    const float2* __restrict__ B = (PHASE == 0) ? g_T  : g_OUT;
    float2* __restrict__ C       = (PHASE == 0) ? g_X  : g_Z;

    __shared__ float2 As[2][16][128];
    __shared__ float2 Bs[2][16][32];

    const int mBase = blockIdx.y * 128;
    const int nBase = blockIdx.x * 32;
    const int tid = threadIdx.x;
    const int mg = tid >> 4;       // 0..15
    const int ng = tid & 15;       // 0..15
    const int m0 = mg * 8, n0 = ng * 2;

    float2 pA2[8], pB2[2];

    auto loadRegs = [&](int k0) {
#pragma unroll
        for (int j = 0; j < 8; j++) {
            int lid = tid + 256 * j;               // 0..2047
            int row = lid >> 4, k = lid & 15;
            pA2[j] = A[(size_t)(mBase + row) * K + k0 + k];
        }
#pragma unroll
        for (int j = 0; j < 2; j++) {
            int lid = tid + 256 * j;               // 0..511
            int kr = lid >> 5, c = lid & 31;
            pB2[j] = B[(size_t)(k0 + kr) * N + nBase + c];
        }
    };
    auto storeRegs = [&](int buf) {
#pragma unroll
        for (int j = 0; j < 8; j++) {
            int lid = tid + 256 * j;
            int row = lid >> 4, k = lid & 15;
            As[buf][k][row] = pA2[j];
        }
#pragma unroll
        for (int j = 0; j < 2; j++) {
            int lid = tid + 256 * j;
            int kr = lid >> 5, c = lid & 31;
            Bs[buf][kr][c] = pB2[j];
        }
    };

    float2 acc[8][2];
#pragma unroll
    for (int i = 0; i < 8; i++) { acc[i][0] = make_float2(0.f, 0.f); acc[i][1] = make_float2(0.f, 0.f); }

    loadRegs(0);
    storeRegs(0);
    __syncthreads();

    for (int t = 0; t < T; t++) {
        if (t + 1 < T) loadRegs((t + 1) * 16);
        const int cur = t & 1;
#pragma unroll
        for (int kk = 0; kk < 16; kk++) {
            float2 b0 = Bs[cur][kk][n0], b1 = Bs[cur][kk][n0 + 1];
#pragma unroll
            for (int i = 0; i < 8; i++) {
                float2 a = As[cur][kk][m0 + i];
                acc[i][0] = cmad(acc[i][0], a, b0);
                acc[i][1] = cmad(acc[i][1], a, b1);
            }
        }
        if (t + 1 < T) storeRegs((t + 1) & 1);
        __syncthreads();
    }

#pragma unroll
    for (int i = 0; i < 8; i++) {
        float4 v = make_float4(acc[i][0].x, acc[i][0].y, acc[i][1].x, acc[i][1].y);
        *(float4*)(C + (size_t)(mBase + m0 + i) * N + nBase + n0) = v;
    }
}

// ---------------------------------------------------------------------------
// Mixing: base tiles (W1 at top (0,0), W2 at bottom (3,0)); 512 blocks.
// ---------------------------------------------------------------------------
__global__ __launch_bounds__(256) void mix_base() {
    __shared__ float2 Xs[512];     // [b][i]
    __shared__ float2 Ws[4096];    // [i][o]
    const int bi = blockIdx.x;
    const int t = bi >> 8, m = bi & 255;
    const int x = m >> 4, y = m & 15;
    const int ki = t ? (112 + x) : x;
    const int kj = y;
    const int tid = threadIdx.x;

    for (int j = tid; j < 512; j += 256)
        Xs[j] = g_X[(size_t)ki * 32768 + j * 64 + kj];
    for (int j = tid; j < 4096; j += 256)
        Ws[j] = g_Wt[(size_t)(t * 256 + m) * 4096 + j];
    __syncthreads();

#pragma unroll
    for (int p = 0; p < 2; p++) {
        int idx = tid + p * 256;
        int b = idx >> 6, o = idx & 63;
        float2 acc = make_float2(0.f, 0.f);
#pragma unroll 8
        for (int i = 0; i < 64; i++)
            acc = cmad(acc, Xs[b * 64 + i], Ws[i * 64 + o]);
        g_OUT[(size_t)ki * 32768 + idx * 64 + kj] = acc;
    }
}

// ---------------------------------------------------------------------------
// Mixing: expert tiles via rank-4 LoRA path.  30 tiles x 256 modes = 7680 blocks.
// out[b,o] = 0.1*sigmoid(gate)* sum_r lb[o,r] * (sum_i X[b,i] la[r,i])
// ---------------------------------------------------------------------------
__global__ __launch_bounds__(64) void mix_expert(
        const float* __restrict__ la1re, const float* __restrict__ la1im,
        const float* __restrict__ la2re, const float* __restrict__ la2im,
        const float* __restrict__ gate1, const float* __restrict__ gate2) {
    __shared__ float2 Xs[512];
    __shared__ float2 La[256];     // [r][i]
    __shared__ float2 P[32];       // [b][r]
    const int bi = blockIdx.x;
    const int s = bi / 3840;
    const int rem = bi - s * 3840;
    const int e = rem >> 8, m = rem & 255;
    const int x = m >> 4, y = m & 15;
    const int gr = (e + 1) >> 2, gc = (e + 1) & 3;
    const int ki = (s == 0) ? (gr * 16 + x) : (64 + (3 - gr) * 16 + x);
    const int kj = gc * 16 + y;
    const int tid = threadIdx.x;

    const float* lre = s ? la2re : la1re;
    const float* lim = s ? la2im : la1im;
    for (int j = tid; j < 512; j += 64)
        Xs[j] = g_X[(size_t)ki * 32768 + j * 64 + kj];
    for (int j = tid; j < 256; j += 64)
        La[j] = make_float2(lre[e * 256 + j], lim[e * 256 + j]);
    __syncthreads();

    if (tid < 32) {
        int b = tid >> 2, r = tid & 3;
        float2 acc = make_float2(0.f, 0.f);
#pragma unroll 8
        for (int i = 0; i < 64; i++)
            acc = cmad(acc, Xs[b * 64 + i], La[r * 64 + i]);
        P[tid] = acc;
    }
    __syncthreads();

    const float gv = s ? gate2[e] : gate1[e];
    const float g = 0.1f / (1.f + expf(-gv));
    const int o = tid;
    float2 lb[4];
    size_t lbOff = ((size_t)(s * 15 + e) * 256 + m) * 256 + o * 4;
#pragma unroll
    for (int r = 0; r < 4; r++) lb[r] = g_LBt[lbOff + r];
#pragma unroll
    for (int b = 0; b < 8; b++) {
        float2 acc = make_float2(0.f, 0.f);
#pragma unroll
        for (int r = 0; r < 4; r++) acc = cmad(acc, P[b * 4 + r], lb[r]);
        acc.x *= g; acc.y *= g;
        g_OUT[(size_t)ki * 32768 + (b * 64 + o) * 64 + kj] = acc;
    }
}

// ---------------------------------------------------------------------------
// sploss = mean(sigmoid(gate1)) + mean(sigmoid(gate2)), written after y.
// ---------------------------------------------------------------------------
__global__ void sploss_kernel(const float* __restrict__ gate1,
                              const float* __restrict__ gate2,
                              float* __restrict__ out, int out_size) {
    const int tid = threadIdx.x;
    float v = 0.f;
    if (tid < 15)
        v = 1.f / (1.f + expf(-gate1[tid])) + 1.f / (1.f + expf(-gate2[tid]));
#pragma unroll
    for (int off = 16; off > 0; off >>= 1)
        v += __shfl_down_sync(0xffffffffu, v, off);
    if (tid == 0) {
        float sp = v / 15.0f;
        for (int i = 33554432; i < out_size; i++) out[i] = sp;
    }
}

// ---------------------------------------------------------------------------
extern "C" void kernel_launch(void* const* d_in, const int* in_sizes, int n_in,
                              void* d_out, int out_size) {
    const float* x     = (const float*)d_in[0];
    const float* w1re  = (const float*)d_in[1];
    const float* w1im  = (const float*)d_in[2];
    const float* w2re  = (const float*)d_in[3];
    const float* w2im  = (const float*)d_in[4];
    const float* la1re = (const float*)d_in[5];
    const float* la1im = (const float*)d_in[6];
    const float* lb1re = (const float*)d_in[7];
    const float* lb1im = (const float*)d_in[8];
    const float* la2re = (const float*)d_in[9];
    const float* la2im = (const float*)d_in[10];
    const float* lb2re = (const float*)d_in[11];
    const float* lb2im = (const float*)d_in[12];
    const float* gate1 = (const float*)d_in[13];
    const float* gate2 = (const float*)d_in[14];
    float* out = (float*)d_out;

    prep_tables<<<128, 256>>>();
    prep_w<<<8192, 256>>>(w1re, w1im, w2re, w2im);
    prep_lb<<<7680, 256>>>(lb1re, lb1im, lb2re, lb2im);

    // K1: forward W-DFT (real -> 64 complex modes), rows = (bc,u)
    sgemm_dft<0><<<dim3(2048, 1), 256>>>(x, nullptr);
    // K2: forward H-DFT (128 band modes)
    cgemm_dft<0><<<dim3(1024, 1), 256>>>();
    // Mixing
    mix_base<<<512, 256>>>();
    mix_expert<<<7680, 64>>>(la1re, la1im, la2re, la2im, gate1, gate2);
    // K3: inverse H-DFT
    cgemm_dft<1><<<dim3(1024, 2), 256>>>();
    // K4: inverse W-DFT with Hermitian fold -> real y
    sgemm_dft<1><<<dim3(2048, 2), 256>>>(nullptr, out);
    // trailing scalar
    sploss_kernel<<<1, 32>>>(gate1, gate2, out, out_size);
}

// round 16
// speedup vs baseline: 1.1722x; 1.1722x over previous
#include <cuda_runtime.h>
#include <math.h>

#define PI_D 3.14159265358979323846

// ---------------------------------------------------------------------------
// Problem constants: B=8, CI=CO=64, H=W=256, M1=M2=16, G=4, RANK=4, NEXP=15
// Active modes: ki index 0..127 -> H-mode (ki<64 ? ki : ki+128); kj 0..63.
// ---------------------------------------------------------------------------

__device__ float2 g_T  [256 * 512 * 64];   // [u][bc][kj]   W-DFT of x
__device__ float2 g_X  [128 * 512 * 64];   // [ki][bc][kj]  full corner spectrum
__device__ float2 g_OUT[128 * 512 * 64];   // [ki][bo][kj]  mixed spectrum
__device__ float2 g_Z  [256 * 512 * 64];   // [u][bo][kj]   inverse H-DFT
__device__ float  g_Bw [256 * 128];        // [v][2kj(+1)]  forward W twiddles
__device__ float2 g_A2 [128 * 256];        // [ki][u]       forward H twiddles
__device__ float2 g_A3 [256 * 128];        // [u][ki]       inverse H twiddles
__device__ float  g_Bi [128 * 256];        // [2kj(+1)][v]  inverse W (Hermitian-folded, /HW)
__device__ float2 g_Wt [2 * 256 * 64 * 64];        // [t][xy][i][o] base weights transposed
__device__ float2 g_LBt[2 * 15 * 256 * 64 * 4];    // [s][e][xy][o][r] lora_b transposed

__device__ __forceinline__ float2 cmad(float2 acc, float2 a, float2 b) {
    acc.x = fmaf(a.x, b.x, fmaf(-a.y, b.y, acc.x));
    acc.y = fmaf(a.x, b.y, fmaf( a.y, b.x, acc.y));
    return acc;
}

// ---------------------------------------------------------------------------
// Twiddle tables (built per launch; deterministic)
// ---------------------------------------------------------------------------
__global__ void prep_tables() {
    int idx = blockIdx.x * 256 + threadIdx.x;   // 0..32767
    const double w = 2.0 * PI_D / 256.0;
    {   // Bw[v][n]: n=2kj -> cos, n=2kj+1 -> -sin  (e^{-i t})
        int v = idx >> 7, n = idx & 127, kj = n >> 1;
        double s, c; sincos(w * ((kj * v) & 255), &s, &c);
        g_Bw[idx] = (n & 1) ? (float)(-s) : (float)c;
    }
    {   // A2[ki][u] = e^{-2pi i m u / 256}
        int ki = idx >> 8, u = idx & 255;
        int m = (ki < 64) ? ki : ki + 128;
        double s, c; sincos(w * ((m * u) & 255), &s, &c);
        g_A2[idx] = make_float2((float)c, (float)(-s));
    }
    {   // A3[u][ki] = e^{+2pi i m u / 256}
        int u = idx >> 7, ki = idx & 127;
        int m = (ki < 64) ? ki : ki + 128;
        double s, c; sincos(w * ((m * u) & 255), &s, &c);
        g_A3[idx] = make_float2((float)c, (float)s);
    }
    {   // Bi[n][v]: y = sum_kj Re*z*C + Im*z*S; C0=inv, Ck=2 inv cos, S0=0, Sk=-2 inv sin
        int n = idx >> 8, v = idx & 255, kj = n >> 1;
        double s, c; sincos(w * ((kj * v) & 255), &s, &c);
        const float inv = 1.0f / 65536.0f;
        float val;
        if ((n & 1) == 0) val = (kj == 0) ? inv : (float)(2.0 * c) * inv;
        else              val = (kj == 0) ? 0.f : (float)(-2.0 * s) * inv;
        g_Bi[idx] = val;
    }
}

// Transpose base weights: w[i][o][xy] -> Wt[t][xy][i*64+o]
__global__ void prep_w(const float* __restrict__ w1re, const float* __restrict__ w1im,
                       const float* __restrict__ w2re, const float* __restrict__ w2im) {
    int idx = blockIdx.x * 256 + threadIdx.x;          // 0 .. 2*256*4096-1
    int t   = idx >> 20;
    int xy  = (idx >> 12) & 255;
    int io  = idx & 4095;
    int i   = io >> 6, o = io & 63;
    int src = i * 16384 + o * 256 + xy;
    const float* re = t ? w2re : w1re;
    const float* im = t ? w2im : w1im;
    g_Wt[idx] = make_float2(re[src], im[src]);
}

// Transpose lora_b: lb[e][o][r][xy] -> LBt[s][e][xy][o*4+r]
__global__ void prep_lb(const float* __restrict__ b1re, const float* __restrict__ b1im,
                        const float* __restrict__ b2re, const float* __restrict__ b2im) {
    int idx = blockIdx.x * 256 + threadIdx.x;          // 0 .. 1966080-1
    int s   = idx / 983040;
    int rem = idx - s * 983040;
    int e   = rem >> 16;
    int rem2 = rem & 65535;
    int xy  = rem2 >> 8;
    int orr = rem2 & 255;
    int o   = orr >> 2, r = orr & 3;
    int src = e * 65536 + o * 1024 + r * 256 + xy;
    const float* re = s ? b2re : b1re;
    const float* im = s ? b2im : b1im;
    g_LBt[idx] = make_float2(re[src], im[src]);
}

// ---------------------------------------------------------------------------
// Real SGEMM, 128x128 block, 16 K-tile, 8x8 microtile, double-buffered.
// MODE 0 (K1):  A = x rows (bc,u), K=256, N=128, C = g_T row perm -> (u,bc)
// MODE 1 (K4):  A = g_Z with row perm (bo,u)->(u,bo), K=128, N=256, C = y natural
// ---------------------------------------------------------------------------
template<int MODE>
__global__ __launch_bounds__(256, 2) void sgemm_dft(const float* __restrict__ Ain,
                                                    float* __restrict__ Cout) {
    const int K = (MODE == 0) ? 256 : 128;
    const int N = (MODE == 0) ? 128 : 256;
    const int T = K / 16;
    const float* __restrict__ A  = (MODE == 0) ? Ain : (const float*)g_Z;
    const float* __restrict__ Bm = (MODE == 0) ? g_Bw : g_Bi;
    float* __restrict__ C        = (MODE == 0) ? (float*)g_T : Cout;

    __shared__ float As[2][16][128];   // [k][m-row]
    __shared__ float Bs[2][16][128];   // [k][n-col]

    const int mBase = blockIdx.x * 128;
    const int nBase = blockIdx.y * 128;
    const int tid = threadIdx.x;
    const int mg = tid >> 4;        // 0..15
    const int ng = tid & 15;        // 0..15
    const int m0 = mg * 8, n0 = ng * 8;

    float4 pA[2], pB[2];

    auto loadRegs = [&](int k0) {
#pragma unroll
        for (int j = 0; j < 2; j++) {
            int lid = tid + 256 * j;               // 0..511
            int row = lid >> 2;                    // 0..127
            int k4  = (lid & 3) * 4;               // 0..12
            int gr  = mBase + row;
            const float* arow;
            if (MODE == 0) arow = A + (size_t)gr * 256;
            else           arow = A + ((size_t)(gr & 255) * 512 + (gr >> 8)) * 128;
            pA[j] = *(const float4*)(arow + k0 + k4);
        }
#pragma unroll
        for (int j = 0; j < 2; j++) {
            int lid = tid + 256 * j;               // 0..511
            int kr  = lid >> 5;                    // 0..15
            int c4  = (lid & 31) * 4;              // 0..124
            pB[j] = *(const float4*)(Bm + (size_t)(k0 + kr) * N + nBase + c4);
        }
    };
    auto storeRegs = [&](int buf) {
#pragma unroll
        for (int j = 0; j < 2; j++) {
            int lid = tid + 256 * j;
            int row = lid >> 2;
            int k4  = (lid & 3) * 4;
            As[buf][k4 + 0][row] = pA[j].x; As[buf][k4 + 1][row] = pA[j].y;
            As[buf][k4 + 2][row] = pA[j].z; As[buf][k4 + 3][row] = pA[j].w;
        }
#pragma unroll
        for (int j = 0; j < 2; j++) {
            int lid = tid + 256 * j;
            int kr  = lid >> 5;
            int c4  = (lid & 31) * 4;
            *(float4*)&Bs[buf][kr][c4] = pB[j];
        }
    };

    float acc[8][8];
#pragma unroll
    for (int i = 0; i < 8; i++)
#pragma unroll
        for (int j = 0; j < 8; j++) acc[i][j] = 0.f;

    loadRegs(0);
    storeRegs(0);
    __syncthreads();

    for (int t = 0; t < T; t++) {
        if (t + 1 < T) loadRegs((t + 1) * 16);
        const int cur = t & 1;
#pragma unroll
        for (int kk = 0; kk < 16; kk++) {
            float4 a0 = *(const float4*)&As[cur][kk][m0];
            float4 a1 = *(const float4*)&As[cur][kk][m0 + 4];
            float4 b0 = *(const float4*)&Bs[cur][kk][n0];
            float4 b1 = *(const float4*)&Bs[cur][kk][n0 + 4];
            float rA[8] = {a0.x, a0.y, a0.z, a0.w, a1.x, a1.y, a1.z, a1.w};
            float rB[8] = {b0.x, b0.y, b0.z, b0.w, b1.x, b1.y, b1.z, b1.w};
#pragma unroll
            for (int i = 0; i < 8; i++)
#pragma unroll
                for (int j = 0; j < 8; j++) acc[i][j] = fmaf(rA[i], rB[j], acc[i][j]);
        }
        if (t + 1 < T) storeRegs((t + 1) & 1);
        __syncthreads();
    }

#pragma unroll
    for (int i = 0; i < 8; i++) {
        int gr = mBase + m0 + i;
        float* crow;
        if (MODE == 0) {
            int bc = gr >> 8, u = gr & 255;
            crow = C + (size_t)(u * 512 + bc) * 128;
        } else {
            crow = C + (size_t)gr * 256;
        }
        *(float4*)(crow + nBase + n0)     = make_float4(acc[i][0], acc[i][1], acc[i][2], acc[i][3]);
        *(float4*)(crow + nBase + n0 + 4) = make_float4(acc[i][4], acc[i][5], acc[i][6], acc[i][7]);
    }
}

// ---------------------------------------------------------------------------
// Complex GEMM: C[M][32768] = A[M][K] * B[K][32768].  128x64 block, 16 K-tile,
// 8x4 complex microtile, double-buffered.
// PHASE 0: K2 (A2 * T -> X), M=128, K=256.  PHASE 1: K3 (A3 * OUT -> Z), M=256, K=128.
// ---------------------------------------------------------------------------
template<int PHASE>
__global__ __launch_bounds__(256, 2) void cgemm_dft() {
    const int K = (PHASE == 0) ? 256 : 128;
    const int N = 32768;
    const int T = K / 16;
    const float2* __restrict__ A = (PHASE == 0) ? g_A2 : g_A3;
    const float2* __restrict__ B = (PHASE == 0) ? g_T  : g_OUT;
    float2* __restrict__ C       = (PHASE == 0) ? g_X  : g_Z;

    __shared__ float2 As[2][16][128];  // [k][m-row]
    __shared__ float2 Bs[2][16][64];   // [k][n-col]

    const int mBase = blockIdx.y * 128;
    const int nBase = blockIdx.x * 64;
    const int tid = threadIdx.x;
    const int mg = tid >> 4;       // 0..15
    const int ng = tid & 15;       // 0..15
    const int m0 = mg * 8, n0 = ng * 4;

    float4 pA[4], pB[2];

    auto loadRegs = [&](int k0) {
#pragma unroll
        for (int j = 0; j < 4; j++) {
            int lid = tid + 256 * j;               // 0..1023
            int row = lid >> 3;                    // 0..127
            int kp  = (lid & 7) * 2;               // 0,2,..,14
            pA[j] = *(const float4*)(A + (size_t)(mBase + row) * K + k0 + kp);
        }
#pragma unroll
        for (int j = 0; j < 2; j++) {
            int lid = tid + 256 * j;               // 0..511
            int kr  = lid >> 5;                    // 0..15
            int c2  = (lid & 31) * 2;              // 0..62
            pB[j] = *(const float4*)(B + (size_t)(k0 + kr) * N + nBase + c2);
        }
    };
    auto storeRegs = [&](int buf) {
#pragma unroll
        for (int j = 0; j < 4; j++) {
            int lid = tid + 256 * j;
            int row = lid >> 3;
            int kp  = (lid & 7) * 2;
            As[buf][kp + 0][row] = make_float2(pA[j].x, pA[j].y);
            As[buf][kp + 1][row] = make_float2(pA[j].z, pA[j].w);
        }
#pragma unroll
        for (int j = 0; j < 2; j++) {
            int lid = tid + 256 * j;
            int kr  = lid >> 5;
            int c2  = (lid & 31) * 2;
            *(float4*)&Bs[buf][kr][c2] = pB[j];
        }
    };

    float2 acc[8][4];
#pragma unroll
    for (int i = 0; i < 8; i++)
#pragma unroll
        for (int j = 0; j < 4; j++) acc[i][j] = make_float2(0.f, 0.f);

    loadRegs(0);
    storeRegs(0);
    __syncthreads();

    for (int t = 0; t < T; t++) {
        if (t + 1 < T) loadRegs((t + 1) * 16);
        const int cur = t & 1;
#pragma unroll
        for (int kk = 0; kk < 16; kk++) {
            float4 av0 = *(const float4*)&As[cur][kk][m0];
            float4 av1 = *(const float4*)&As[cur][kk][m0 + 2];
            float4 av2 = *(const float4*)&As[cur][kk][m0 + 4];
            float4 av3 = *(const float4*)&As[cur][kk][m0 + 6];
            float4 bv0 = *(const float4*)&Bs[cur][kk][n0];
            float4 bv1 = *(const float4*)&Bs[cur][kk][n0 + 2];
            float2 a[8] = {
                make_float2(av0.x, av0.y), make_float2(av0.z, av0.w),
                make_float2(av1.x, av1.y), make_float2(av1.z, av1.w),
                make_float2(av2.x, av2.y), make_float2(av2.z, av2.w),
                make_float2(av3.x, av3.y), make_float2(av3.z, av3.w)};
            float2 b[4] = {
                make_float2(bv0.x, bv0.y), make_float2(bv0.z, bv0.w),
                make_float2(bv1.x, bv1.y), make_float2(bv1.z, bv1.w)};
#pragma unroll
            for (int i = 0; i < 8; i++)
#pragma unroll
                for (int j = 0; j < 4; j++) acc[i][j] = cmad(acc[i][j], a[i], b[j]);
        }
        if (t + 1 < T) storeRegs((t + 1) & 1);
        __syncthreads();
    }

#pragma unroll
    for (int i = 0; i < 8; i++) {
        float2* crow = C + (size_t)(mBase + m0 + i) * N + nBase + n0;
        *(float4*)(crow)     = make_float4(acc[i][0].x, acc[i][0].y, acc[i][1].x, acc[i][1].y);
        *(float4*)(crow + 2) = make_float4(acc[i][2].x, acc[i][2].y, acc[i][3].x, acc[i][3].y);
    }
}

// ---------------------------------------------------------------------------
// Mixing: base tiles (W1 at top (0,0), W2 at bottom (3,0)); 512 blocks.
// ---------------------------------------------------------------------------
__global__ __launch_bounds__(256) void mix_base() {
    __shared__ float2 Xs[512];     // [b][i]
    __shared__ float2 Ws[4096];    // [i][o]
    const int bi = blockIdx.x;
    const int t = bi >> 8, m = bi & 255;
    const int x = m >> 4, y = m & 15;
    const int ki = t ? (112 + x) : x;
    const int kj = y;
    const int tid = threadIdx.x;

    for (int j = tid; j < 512; j += 256)
        Xs[j] = g_X[(size_t)ki * 32768 + j * 64 + kj];
    for (int j = tid; j < 4096; j += 256)
        Ws[j] = g_Wt[(size_t)(t * 256 + m) * 4096 + j];
    __syncthreads();

#pragma unroll
    for (int p = 0; p < 2; p++) {
        int idx = tid + p * 256;
        int b = idx >> 6, o = idx & 63;
        float2 acc = make_float2(0.f, 0.f);
#pragma unroll 8
        for (int i = 0; i < 64; i++)
            acc = cmad(acc, Xs[b * 64 + i], Ws[i * 64 + o]);
        g_OUT[(size_t)ki * 32768 + idx * 64 + kj] = acc;
    }
}

// ---------------------------------------------------------------------------
// Mixing: expert tiles via rank-4 LoRA path.  30 tiles x 256 modes = 7680 blocks.
// out[b,o] = 0.1*sigmoid(gate)* sum_r lb[o,r] * (sum_i X[b,i] la[r,i])
// ---------------------------------------------------------------------------
__global__ __launch_bounds__(64) void mix_expert(
        const float* __restrict__ la1re, const float* __restrict__ la1im,
        const float* __restrict__ la2re, const float* __restrict__ la2im,
        const float* __restrict__ gate1, const float* __restrict__ gate2) {
    __shared__ float2 Xs[512];
    __shared__ float2 La[256];     // [r][i]
    __shared__ float2 P[32];       // [b][r]
    const int bi = blockIdx.x;
    const int s = bi / 3840;
    const int rem = bi - s * 3840;
    const int e = rem >> 8, m = rem & 255;
    const int x = m >> 4, y = m & 15;
    const int gr = (e + 1) >> 2, gc = (e + 1) & 3;
    const int ki = (s == 0) ? (gr * 16 + x) : (64 + (3 - gr) * 16 + x);
    const int kj = gc * 16 + y;
    const int tid = threadIdx.x;

    const float* lre = s ? la2re : la1re;
    const float* lim = s ? la2im : la1im;
    for (int j = tid; j < 512; j += 64)
        Xs[j] = g_X[(size_t)ki * 32768 + j * 64 + kj];
    for (int j = tid; j < 256; j += 64)
        La[j] = make_float2(lre[e * 256 + j], lim[e * 256 + j]);
    __syncthreads();

    if (tid < 32) {
        int b = tid >> 2, r = tid & 3;
        float2 acc = make_float2(0.f, 0.f);
#pragma unroll 8
        for (int i = 0; i < 64; i++)
            acc = cmad(acc, Xs[b * 64 + i], La[r * 64 + i]);
        P[tid] = acc;
    }
    __syncthreads();

    const float gv = s ? gate2[e] : gate1[e];
    const float g = 0.1f / (1.f + expf(-gv));
    const int o = tid;
    float2 lb[4];
    size_t lbOff = ((size_t)(s * 15 + e) * 256 + m) * 256 + o * 4;
#pragma unroll
    for (int r = 0; r < 4; r++) lb[r] = g_LBt[lbOff + r];
#pragma unroll
    for (int b = 0; b < 8; b++) {
        float2 acc = make_float2(0.f, 0.f);
#pragma unroll
        for (int r = 0; r < 4; r++) acc = cmad(acc, P[b * 4 + r], lb[r]);
        acc.x *= g; acc.y *= g;
        g_OUT[(size_t)ki * 32768 + (b * 64 + o) * 64 + kj] = acc;
    }
}

// ---------------------------------------------------------------------------
// sploss = mean(sigmoid(gate1)) + mean(sigmoid(gate2)), written after y.
// ---------------------------------------------------------------------------
__global__ void sploss_kernel(const float* __restrict__ gate1,
                              const float* __restrict__ gate2,
                              float* __restrict__ out, int out_size) {
    const int tid = threadIdx.x;
    float v = 0.f;
    if (tid < 15)
        v = 1.f / (1.f + expf(-gate1[tid])) + 1.f / (1.f + expf(-gate2[tid]));
#pragma unroll
    for (int off = 16; off > 0; off >>= 1)
        v += __shfl_down_sync(0xffffffffu, v, off);
    if (tid == 0) {
        float sp = v / 15.0f;
        for (int i = 33554432; i < out_size; i++) out[i] = sp;
    }
}

// ---------------------------------------------------------------------------
extern "C" void kernel_launch(void* const* d_in, const int* in_sizes, int n_in,
                              void* d_out, int out_size) {
    const float* x     = (const float*)d_in[0];
    const float* w1re  = (const float*)d_in[1];
    const float* w1im  = (const float*)d_in[2];
    const float* w2re  = (const float*)d_in[3];
    const float* w2im  = (const float*)d_in[4];
    const float* la1re = (const float*)d_in[5];
    const float* la1im = (const float*)d_in[6];
    const float* lb1re = (const float*)d_in[7];
    const float* lb1im = (const float*)d_in[8];
    const float* la2re = (const float*)d_in[9];
    const float* la2im = (const float*)d_in[10];
    const float* lb2re = (const float*)d_in[11];
    const float* lb2im = (const float*)d_in[12];
    const float* gate1 = (const float*)d_in[13];
    const float* gate2 = (const float*)d_in[14];
    float* out = (float*)d_out;

    prep_tables<<<128, 256>>>();
    prep_w<<<8192, 256>>>(w1re, w1im, w2re, w2im);
    prep_lb<<<7680, 256>>>(lb1re, lb1im, lb2re, lb2im);

    // K1: forward W-DFT (real -> 64 complex modes), rows = (bc,u)
    sgemm_dft<0><<<dim3(1024, 1), 256>>>(x, nullptr);
    // K2: forward H-DFT (128 band modes)
    cgemm_dft<0><<<dim3(512, 1), 256>>>();
    // Mixing
    mix_base<<<512, 256>>>();
    mix_expert<<<7680, 64>>>(la1re, la1im, la2re, la2im, gate1, gate2);
    // K3: inverse H-DFT
    cgemm_dft<1><<<dim3(512, 2), 256>>>();
    // K4: inverse W-DFT with Hermitian fold -> real y
    sgemm_dft<1><<<dim3(1024, 2), 256>>>(nullptr, out);
    // trailing scalar
    sploss_kernel<<<1, 32>>>(gate1, gate2, out, out_size);
}